// round 6
// baseline (speedup 1.0000x reference)
#include <cuda_runtime.h>
#include <cstdint>

// AdaptiveSample, two-kernel split:
//   K1: per-pixel softmax weights over 15 sampled taps -> scratch [b][s][h][w]
//   K2: barrier-free gather: out[b,c,h,w] = sum_s wv[s]*feat[b,c,h+dy_s,w+dx_s]
//       + passthrough copy of features.

namespace {
constexpr int H  = 256;
constexpr int W  = 512;
constexpr int C  = 32;
constexpr int B  = 2;
constexpr int S  = 15;
constexpr int KS = 5;
constexpr int KK = 25;
constexpr int HW = H * W;

constexpr int BW = 32;
constexpr int BH = 8;
constexpr int NT = BW * BH;
constexpr int GBUF = BH * BW * KK;  // guide tile floats (6400)
}

__device__ float g_weights[B * S * HW];   // 15.7 MB scratch

// ---------------- K1: weights ----------------
__global__ __launch_bounds__(NT, 4)
void weights_kernel(const float* __restrict__ depth,
                    const float* __restrict__ guide,
                    const int*   __restrict__ sidx)
{
    __shared__ float       shg[GBUF];
    __shared__ float       sh_posw[S];
    __shared__ int         sh_k[S];
    __shared__ signed char sh_dy[S], sh_dx[S];

    const int tx  = threadIdx.x;
    const int ty  = threadIdx.y;
    const int tid = ty * BW + tx;
    const int w0  = blockIdx.x * BW;
    const int h0  = blockIdx.y * BH;
    const int b   = blockIdx.z;

    if (tid == 0) {
        float pw[S];
        float sum = 0.f;
        #pragma unroll
        for (int s = 0; s < S; ++s) {
            int k  = sidx[s];
            int px = k % KS;
            int py = k / KS;
            float fx = (float)px - 2.f;
            float fy = (float)py - 2.f;
            float v  = __expf(-0.5f * sqrtf(fx * fx + fy * fy));
            pw[s] = v; sum += v;
            sh_k[s]  = k;
            sh_dy[s] = (signed char)(py - 2);
            sh_dx[s] = (signed char)(px - 2);
        }
        float inv = 1.f / sum;
        #pragma unroll
        for (int s = 0; s < S; ++s) sh_posw[s] = pw[s] * inv;
    }

    // stage guide tile (contiguous float4 rows)
    #pragma unroll
    for (int it = 0; it < (GBUF / 4 + NT - 1) / NT; ++it) {
        int i4 = tid + it * NT;
        if (i4 < GBUF / 4) {
            int row = i4 / (BW * KK / 4);
            int in4 = i4 - row * (BW * KK / 4);
            const float4* src = reinterpret_cast<const float4*>(
                guide + (((size_t)b * H + (h0 + row)) * W + w0) * KK) + in4;
            reinterpret_cast<float4*>(shg + row * BW * KK)[in4] = *src;
        }
    }
    __syncthreads();

    const int h = h0 + ty;
    const int w = w0 + tx;

    const float* drow = depth + (size_t)b * HW;
    const float* gpix = shg + (ty * BW + tx) * KK;   // lane stride 25: conflict-free

    float wv[S];
    unsigned ibm  = 0u;
    float    gmax = 0.f;  // logits >= 0
    #pragma unroll
    for (int s = 0; s < S; ++s) {
        int dy = (int)sh_dy[s], dx = (int)sh_dx[s];
        int hh = h + dy, ww = w + dx;
        bool ib = ((unsigned)hh < (unsigned)H) && ((unsigned)ww < (unsigned)W);
        float d = ib ? __ldg(drow + hh * W + ww) : 0.f;
        bool valid = ib && (d > 0.f) && (d < 192.0f);
        float logit = valid ? sh_posw[s] * gpix[sh_k[s]] : 0.f;
        wv[s] = logit;
        gmax  = fmaxf(gmax, logit);
        ibm  |= (unsigned)ib << s;
    }
    float esum = 0.f;
    #pragma unroll
    for (int s = 0; s < S; ++s) { wv[s] = __expf(wv[s] - gmax); esum += wv[s]; }
    float inv = 1.f / esum;

    float* wout = g_weights + (size_t)b * S * HW + (size_t)h * W + w;
    #pragma unroll
    for (int s = 0; s < S; ++s) {
        float v = ((ibm >> s) & 1u) ? wv[s] * inv : 0.f;  // OOB tap == zero-pad
        wout[(size_t)s * HW] = v;
    }
}

// ---------------- K2: gather + copy (no smem, no barriers) ----------------
__global__ __launch_bounds__(NT, 6)
void gather_kernel(const float* __restrict__ features,
                   const int*   __restrict__ sidx,
                   float* __restrict__ out,
                   float* __restrict__ outf,
                   int do_copy)
{
    const int tx  = threadIdx.x;
    const int ty  = threadIdx.y;
    const int tid = ty * BW + tx;
    const int w0  = blockIdx.x * BW;
    const int h0  = blockIdx.y * BH;
    const int b   = blockIdx.z;

    const int h = h0 + ty;
    const int w = w0 + tx;

    // tap offsets (OOB-clamped; weight is 0 there)
    int offs[S];
    #pragma unroll
    for (int s = 0; s < S; ++s) {
        int k  = __ldg(sidx + s);
        int dy = k / KS - 2;
        int dx = k % KS - 2;
        int hh = h + dy, ww = w + dx;
        bool ib = ((unsigned)hh < (unsigned)H) && ((unsigned)ww < (unsigned)W);
        offs[s] = ib ? (dy * W + dx) : 0;
    }

    const size_t pix   = (size_t)h * W + w;
    const float* fbase = features + (size_t)b * C * HW;
    const float* fpix  = fbase + pix;
    const float* wpix  = g_weights + (size_t)b * S * HW + pix;
    float*       opix  = out + (size_t)b * C * HW + pix;

    #pragma unroll 1
    for (int ct = 0; ct < C / 8; ++ct) {
        const float* fc = fpix + (size_t)(ct * 8) * HW;
        float a0 = 0.f, a1 = 0.f, a2 = 0.f, a3 = 0.f;
        float a4 = 0.f, a5 = 0.f, a6 = 0.f, a7 = 0.f;
        #pragma unroll
        for (int s = 0; s < S; ++s) {
            float wt = __ldg(wpix + (size_t)s * HW);   // coalesced, L1/L2-hot
            int   o  = offs[s];
            a0 = fmaf(wt, __ldg(fc + 0 * HW + o), a0);
            a1 = fmaf(wt, __ldg(fc + 1 * HW + o), a1);
            a2 = fmaf(wt, __ldg(fc + 2 * HW + o), a2);
            a3 = fmaf(wt, __ldg(fc + 3 * HW + o), a3);
            a4 = fmaf(wt, __ldg(fc + 4 * HW + o), a4);
            a5 = fmaf(wt, __ldg(fc + 5 * HW + o), a5);
            a6 = fmaf(wt, __ldg(fc + 6 * HW + o), a6);
            a7 = fmaf(wt, __ldg(fc + 7 * HW + o), a7);
        }
        float* oc = opix + (size_t)(ct * 8) * HW;
        oc[0 * HW] = a0; oc[1 * HW] = a1; oc[2 * HW] = a2; oc[3 * HW] = a3;
        oc[4 * HW] = a4; oc[5 * HW] = a5; oc[6 * HW] = a6; oc[7 * HW] = a7;
    }

    // passthrough copy, float4 both sides (tile is L2-hot)
    if (do_copy) {
        float* ocbase = outf + (size_t)b * C * HW;
        #pragma unroll
        for (int it = 0; it < (C * BH * BW / 4) / NT; ++it) {   // 8
            int i   = tid + it * NT;
            int c   = i >> 6;
            int rem = i & 63;
            int r   = rem >> 3;
            int q4  = rem & 7;
            size_t off = (size_t)c * HW + (size_t)(h0 + r) * W + w0 + q4 * 4;
            float4 v = __ldg(reinterpret_cast<const float4*>(fbase + off));
            *reinterpret_cast<float4*>(ocbase + off) = v;
        }
    }
}

extern "C" void kernel_launch(void* const* d_in, const int* in_sizes, int n_in,
                              void* d_out, int out_size)
{
    const float* depth    = (const float*)d_in[0];
    const float* features = (const float*)d_in[1];
    const float* guide    = (const float*)d_in[2];
    const int*   sidx     = (const int*)d_in[3];

    float* out = (float*)d_out;
    const int featN = in_sizes[1];                       // B*C*H*W
    const int do_copy = (out_size >= 2 * featN) ? 1 : 0; // tuple output: (out, features)
    float* outf = out + featN;

    dim3 block(BW, BH);
    dim3 grid(W / BW, H / BH, B);
    weights_kernel<<<grid, block>>>(depth, guide, sidx);
    gather_kernel<<<grid, block>>>(features, sidx, out, outf, do_copy);
}

// round 7
// speedup vs baseline: 1.1316x; 1.1316x over previous
#include <cuda_runtime.h>
#include <cstdint>

// AdaptiveSample, fused single kernel:
//   weights (softmax over 15 sampled taps of valid*posw*guide) held in registers,
//   then barrier-free direct-LDG gather with 8-channel accumulator tiles,
//   plus float4 passthrough copy of features.

namespace {
constexpr int H  = 256;
constexpr int W  = 512;
constexpr int C  = 32;
constexpr int B  = 2;
constexpr int S  = 15;
constexpr int KS = 5;
constexpr int KK = 25;
constexpr int HW = H * W;

constexpr int BW = 32;
constexpr int BH = 8;
constexpr int NT = BW * BH;
constexpr int GBUF = BH * BW * KK;  // guide tile floats (6400)
}

__global__ __launch_bounds__(NT, 5)
void adaptive_sample_kernel(const float* __restrict__ depth,
                            const float* __restrict__ features,
                            const float* __restrict__ guide,
                            const int*   __restrict__ sidx,
                            float* __restrict__ out,
                            float* __restrict__ outf,
                            int do_copy)
{
    __shared__ float       shg[GBUF];
    __shared__ float       sh_posw[S];
    __shared__ int         sh_k[S];
    __shared__ signed char sh_dy[S], sh_dx[S];

    const int tx  = threadIdx.x;
    const int ty  = threadIdx.y;
    const int tid = ty * BW + tx;
    const int w0  = blockIdx.x * BW;
    const int h0  = blockIdx.y * BH;
    const int b   = blockIdx.z;

    // ---- tap metadata (one thread; S=15 trivial) ----
    if (tid == 0) {
        float pw[S];
        float sum = 0.f;
        #pragma unroll
        for (int s = 0; s < S; ++s) {
            int k  = sidx[s];
            int px = k % KS;
            int py = k / KS;
            float fx = (float)px - 2.f;
            float fy = (float)py - 2.f;
            float v  = __expf(-0.5f * sqrtf(fx * fx + fy * fy));
            pw[s] = v; sum += v;
            sh_k[s]  = k;
            sh_dy[s] = (signed char)(py - 2);
            sh_dx[s] = (signed char)(px - 2);
        }
        float inv = 1.f / sum;
        #pragma unroll
        for (int s = 0; s < S; ++s) sh_posw[s] = pw[s] * inv;
    }

    // ---- stage guide tile (contiguous float4 rows) ----
    #pragma unroll
    for (int it = 0; it < (GBUF / 4 + NT - 1) / NT; ++it) {
        int i4 = tid + it * NT;
        if (i4 < GBUF / 4) {
            int row = i4 / (BW * KK / 4);
            int in4 = i4 - row * (BW * KK / 4);
            const float4* src = reinterpret_cast<const float4*>(
                guide + (((size_t)b * H + (h0 + row)) * W + w0) * KK) + in4;
            reinterpret_cast<float4*>(shg + row * BW * KK)[in4] = *src;
        }
    }
    __syncthreads();   // the only barrier

    const int h = h0 + ty;
    const int w = w0 + tx;

    // ---- per-pixel softmax weights (registers) + gmem tap offsets ----
    const float* drow = depth + (size_t)b * HW;
    const float* gpix = shg + (ty * BW + tx) * KK;   // lane stride 25: conflict-free

    float wv[S];
    int   offs[S];
    unsigned ibm  = 0u;
    float    gmax = 0.f;  // logits >= 0
    #pragma unroll
    for (int s = 0; s < S; ++s) {
        int dy = (int)sh_dy[s], dx = (int)sh_dx[s];
        int hh = h + dy, ww = w + dx;
        bool ib = ((unsigned)hh < (unsigned)H) && ((unsigned)ww < (unsigned)W);
        float d = ib ? __ldg(drow + hh * W + ww) : 0.f;
        bool valid = ib && (d > 0.f) && (d < 192.0f);
        float logit = valid ? sh_posw[s] * gpix[sh_k[s]] : 0.f;
        wv[s] = logit;
        gmax  = fmaxf(gmax, logit);
        ibm  |= (unsigned)ib << s;
        offs[s] = ib ? (dy * W + dx) : 0;   // clamped: weight is 0 there
    }
    float esum = 0.f;
    #pragma unroll
    for (int s = 0; s < S; ++s) { wv[s] = __expf(wv[s] - gmax); esum += wv[s]; }
    float inv = 1.f / esum;
    #pragma unroll
    for (int s = 0; s < S; ++s)
        wv[s] = ((ibm >> s) & 1u) ? wv[s] * inv : 0.f;  // OOB tap == zero-padded feature

    // ---- barrier-free gather: 4 tiles of 8 channels, 8-way MLP ----
    const size_t pix   = (size_t)h * W + w;
    const float* fbase = features + (size_t)b * C * HW;
    const float* fpix  = fbase + pix;
    float*       opix  = out + (size_t)b * C * HW + pix;

    #pragma unroll 1
    for (int ct = 0; ct < C / 8; ++ct) {
        const float* fc = fpix + (size_t)(ct * 8) * HW;
        float a0 = 0.f, a1 = 0.f, a2 = 0.f, a3 = 0.f;
        float a4 = 0.f, a5 = 0.f, a6 = 0.f, a7 = 0.f;
        #pragma unroll
        for (int s = 0; s < S; ++s) {
            float wt = wv[s];
            int   o  = offs[s];
            a0 = fmaf(wt, __ldg(fc + 0 * HW + o), a0);
            a1 = fmaf(wt, __ldg(fc + 1 * HW + o), a1);
            a2 = fmaf(wt, __ldg(fc + 2 * HW + o), a2);
            a3 = fmaf(wt, __ldg(fc + 3 * HW + o), a3);
            a4 = fmaf(wt, __ldg(fc + 4 * HW + o), a4);
            a5 = fmaf(wt, __ldg(fc + 5 * HW + o), a5);
            a6 = fmaf(wt, __ldg(fc + 6 * HW + o), a6);
            a7 = fmaf(wt, __ldg(fc + 7 * HW + o), a7);
        }
        float* oc = opix + (size_t)(ct * 8) * HW;
        oc[0 * HW] = a0; oc[1 * HW] = a1; oc[2 * HW] = a2; oc[3 * HW] = a3;
        oc[4 * HW] = a4; oc[5 * HW] = a5; oc[6 * HW] = a6; oc[7 * HW] = a7;
    }

    // ---- passthrough copy, float4 both sides (tile is L2-hot) ----
    if (do_copy) {
        float* ocbase = outf + (size_t)b * C * HW;
        #pragma unroll
        for (int it = 0; it < (C * BH * BW / 4) / NT; ++it) {   // 8
            int i   = tid + it * NT;
            int c   = i >> 6;
            int rem = i & 63;
            int r   = rem >> 3;
            int q4  = rem & 7;
            size_t off = (size_t)c * HW + (size_t)(h0 + r) * W + w0 + q4 * 4;
            float4 v = __ldg(reinterpret_cast<const float4*>(fbase + off));
            *reinterpret_cast<float4*>(ocbase + off) = v;
        }
    }
}

extern "C" void kernel_launch(void* const* d_in, const int* in_sizes, int n_in,
                              void* d_out, int out_size)
{
    const float* depth    = (const float*)d_in[0];
    const float* features = (const float*)d_in[1];
    const float* guide    = (const float*)d_in[2];
    const int*   sidx     = (const int*)d_in[3];

    float* out = (float*)d_out;
    const int featN = in_sizes[1];                       // B*C*H*W
    const int do_copy = (out_size >= 2 * featN) ? 1 : 0; // tuple output: (out, features)
    float* outf = out + featN;

    dim3 block(BW, BH);
    dim3 grid(W / BW, H / BH, B);
    adaptive_sample_kernel<<<grid, block>>>(depth, features, guide, sidx,
                                            out, outf, do_copy);
}